// round 12
// baseline (speedup 1.0000x reference)
#include <cuda_runtime.h>
#include <math.h>

// Problem constants (fixed by the reference)
#define B_FRAMES 256
#define N_COLS   576
#define MR_ROWS  144
#define Z_LIFT   24
#define N_IT     3
#define ROW_DEG  15
#define N_MSG    (MR_ROWS * ROW_DEG)   // 2160
#define NB_A     ((MR_ROWS / Z_LIFT) * (N_COLS / Z_LIFT) * N_IT)  // 432
#define NCHUNK   (N_COLS / 32)         // 18 column chunks per row

#define FPB   2                        // frames per CTA
#define BT    512                      // threads per CTA (256 per frame)
#define GRID  (B_FRAMES / FPB)         // 128 CTAs -> 1 per SM, single wave
#define NPASS (MR_ROWS / 16)           // 9 row passes (16-lane groups)

#define CE_STRIDE 16                   // per-column list: [0]=deg, [1..15]=edge ids

// Graph structure scratch (rebuilt from H every launch; fully overwritten)
__device__ int g_row_cols[N_MSG];                    // CSR: 15 col ids per row (ascending)
__device__ unsigned g_row_mask[MR_ROWS][NCHUNK];     // per-row 32-col occupancy bitmask
__device__ unsigned char g_row_pref8[MR_ROWS][NCHUNK]; // #ones in row before this chunk

// ---------------------------------------------------------------------------
// Kernel 1: row extraction. One warp per check row; 18 chunk loads issued
// up-front (MLP=18), then ballot-compact. Also emits bitmasks + prefix counts.
// ---------------------------------------------------------------------------
__global__ void nms_prep_rows(const int* __restrict__ H) {
    int warp = (blockIdx.x * blockDim.x + threadIdx.x) >> 5;
    int lane = threadIdx.x & 31;
    if (warp >= MR_ROWS) return;
    const int* row = H + warp * N_COLS;

    int vals[NCHUNK];
    #pragma unroll
    for (int j = 0; j < NCHUNK; ++j) vals[j] = row[j * 32 + lane];

    int cnt = 0;
    #pragma unroll
    for (int j = 0; j < NCHUNK; ++j) {
        unsigned ball = __ballot_sync(0xffffffffu, vals[j] != 0);
        if (lane == 0) {
            g_row_mask[warp][j]  = ball;
            g_row_pref8[warp][j] = (unsigned char)cnt;
        }
        int before = __popc(ball & ((1u << lane) - 1u));
        if (vals[j] != 0) g_row_cols[warp * ROW_DEG + cnt + before] = j * 32 + lane;
        cnt += __popc(ball);
    }
}

// ---------------------------------------------------------------------------
// Kernel 2: decoder. 2 frames/CTA, 16 lanes per check row, no atomics.
// The per-column edge lists are built IN the prologue of every CTA from the
// 13 KB bitmask structure (the standalone single-CTA colbuild kernel was the
// ~20us sink). Bitmasks are staged into the s_E region (dead until iter 0).
// ---------------------------------------------------------------------------
__global__ __launch_bounds__(BT) void nms_decode(
    const float* __restrict__ r,
    const float* __restrict__ alpha,
    const float* __restrict__ beta,
    float* __restrict__ out)
{
    // s_E region doubles as the mask/pref staging area during the prologue.
    __shared__ __align__(16) char s_scratch[FPB * N_MSG * 4];     // 17280 B
    __shared__ float s_sumE[FPB][N_COLS];                         // 4608 B
    __shared__ float s_r[FPB][N_COLS];                            // 4608 B
    __shared__ unsigned short s_ce16[N_COLS * CE_STRIDE];         // 18432 B
    __shared__ float s_a[NB_A];                                   // 1728 B
    __shared__ float s_b[NB_A];                                   // 1728 B

    float (*s_E)[N_MSG] = (float (*)[N_MSG])s_scratch;
    unsigned* p_mask = (unsigned*)s_scratch;                       // [144*18]
    unsigned char* p_pref = (unsigned char*)(s_scratch + MR_ROWS * NCHUNK * 4);

    const int tid    = threadIdx.x;
    const int f      = tid >> 8;           // frame within CTA
    const int ft     = tid & 255;          // thread id within frame
    const int grp    = ft >> 4;            // 16-lane row group (0..15)
    const int k      = ft & 15;            // edge slot (15 = padding)
    const int b      = blockIdx.x * FPB + f;
    const bool act   = (k < ROW_DEG);
    const unsigned hmask = 0xFFFFu << (tid & 16);

    // ---- stage inputs + graph bitmasks ----
    for (int i = tid; i < MR_ROWS * NCHUNK; i += BT) {
        p_mask[i] = g_row_mask[0][i];
        p_pref[i] = g_row_pref8[0][i];
    }
    for (int i = tid; i < NB_A; i += BT) { s_a[i] = alpha[i]; s_b[i] = beta[i]; }
    for (int i = ft; i < N_COLS; i += 256) {
        s_r[f][i] = r[b * N_COLS + i];
        s_sumE[f][i] = 0.0f;
    }
    __syncthreads();

    // ---- build per-column edge lists (ascending row order -> deterministic) ----
    for (int c = tid; c < N_COLS; c += BT) {
        const int cw = c >> 5, cb = c & 31;
        const unsigned below = (1u << cb) - 1u;
        int deg = 0;
        unsigned short* ce = &s_ce16[c * CE_STRIDE];
        #pragma unroll 8
        for (int m = 0; m < MR_ROWS; ++m) {
            unsigned rm = p_mask[m * NCHUNK + cw];
            if ((rm >> cb) & 1u) {
                int slot = (int)p_pref[m * NCHUNK + cw] + __popc(rm & below);
                ++deg;
                if (deg < CE_STRIDE) ce[deg] = (unsigned short)(m * ROW_DEG + slot);
            }
        }
        ce[0] = (unsigned short)deg;
    }

    // ---- per-edge register state (9 edges per thread) ----
    int   rc[NPASS];
    int   aoff[NPASS];
    float rv[NPASS];
    float Ep[NPASS];
    #pragma unroll
    for (int p = 0; p < NPASS; ++p) {
        int row = p * 16 + grp;
        int e = row * ROW_DEG + (act ? k : 0);
        rc[p]   = act ? g_row_cols[e] : 0;
        aoff[p] = (row / Z_LIFT) * ((N_COLS / Z_LIFT) * N_IT)
                + (rc[p] / Z_LIFT) * N_IT;
        Ep[p]   = 0.0f;
    }
    __syncthreads();                       // masks consumed; s_E region now free
    #pragma unroll
    for (int p = 0; p < NPASS; ++p) rv[p] = s_r[f][rc[p]];

    for (int it = 0; it < N_IT; ++it) {
        // ---- check-node phase (edge-parallel, writes s_E) ----
        #pragma unroll
        for (int p = 0; p < NPASS; ++p) {
            float v = rv[p] + s_sumE[f][rc[p]] - Ep[p];   // v->c message
            float av = act ? fabsf(v) : INFINITY;

            // sign parity of the 16-lane row group (one ballot, both halves)
            unsigned negb = __ballot_sync(0xffffffffu, act && (v < 0.0f));
            int parity = __popc(negb & hmask) & 1;

            // min1/min2/argmin butterfly over the 16-lane group (uniform code)
            float m1 = av, m2 = INFINITY;
            int   k1 = k;
            #pragma unroll
            for (int d = 1; d < 16; d <<= 1) {
                float om1 = __shfl_xor_sync(0xffffffffu, m1, d, 16);
                float om2 = __shfl_xor_sync(0xffffffffu, m2, d, 16);
                int   ok1 = __shfl_xor_sync(0xffffffffu, k1, d, 16);
                if (om1 < m1) { m2 = fminf(m1, om2); m1 = om1; k1 = ok1; }
                else          { m2 = fminf(m2, om1); }
            }

            if (act) {
                float sel = (k == k1) ? m2 : m1;          // exclude self at argmin
                int   ai  = aoff[p] + it;
                float mag = fmaxf(sel - s_b[ai], 0.0f);
                int neg = parity ^ ((v < 0.0f) ? 1 : 0);
                float E = s_a[ai] * mag;
                E = neg ? -E : E;
                E = (m1 == 0.0f) ? 0.0f : E;              // any zero in row -> E = 0
                Ep[p] = E;
                s_E[f][(p * 16 + grp) * ROW_DEG + k] = E;
            }
        }
        __syncthreads();

        // ---- column-sum phase: fixed-stride list gather (no atomics) ----
        for (int c = ft; c < N_COLS; c += 256) {
            const unsigned short* ce = &s_ce16[c * CE_STRIDE];
            int deg = ce[0];
            float s = 0.0f;
            for (int j = 1; j <= deg; ++j) s += s_E[f][ce[j]];
            s_sumE[f][c] = s;
        }
        __syncthreads();
    }

    // Posterior LLRs
    for (int i = ft; i < N_COLS; i += 256)
        out[b * N_COLS + i] = s_r[f][i] + s_sumE[f][i];
}

extern "C" void kernel_launch(void* const* d_in, const int* in_sizes, int n_in,
                              void* d_out, int out_size) {
    const float* r     = (const float*)d_in[0];   // (256, 576)
    const float* alpha = (const float*)d_in[1];   // (6, 24, 3)
    const float* beta  = (const float*)d_in[2];   // (6, 24, 3)
    const int*   H     = (const int*)d_in[3];     // (144, 576)
    float* out = (float*)d_out;                   // (256, 576)

    nms_prep_rows<<<18, 256>>>(H);
    nms_decode<<<GRID, BT>>>(r, alpha, beta, out);
}

// round 13
// speedup vs baseline: 1.7939x; 1.7939x over previous
#include <cuda_runtime.h>
#include <math.h>

// Problem constants (fixed by the reference)
#define B_FRAMES 256
#define N_COLS   576
#define MR_ROWS  144
#define Z_LIFT   24
#define N_IT     3
#define ROW_DEG  15
#define N_MSG    (MR_ROWS * ROW_DEG)   // 2160
#define NB_A     ((MR_ROWS / Z_LIFT) * (N_COLS / Z_LIFT) * N_IT)  // 432
#define NCHUNK   (N_COLS / 32)         // 18 column chunks per row

#define BT    256                      // decode threads per CTA (1 frame/CTA)
#define NPASS (MR_ROWS / 16)           // 9 row passes (16-lane groups)
#define CE_STRIDE 16                   // per-column list: [0]=deg, [1..]=edge ids

// Graph structure scratch (rebuilt from H each launch)
__device__ int g_row_cols[N_MSG];                      // CSR: 15 col ids per row (ascending)
__device__ unsigned g_row_mask[MR_ROWS][NCHUNK];       // per-row 32-col occupancy bitmask
__device__ unsigned char g_row_pref8[MR_ROWS][NCHUNK]; // #ones in row before this chunk
__device__ __align__(16) unsigned short g_ce16[N_COLS * CE_STRIDE]; // col lists

// ---------------------------------------------------------------------------
// Kernel 1: row extraction. One warp per row; 18 chunk loads batched (MLP=18).
// ---------------------------------------------------------------------------
__global__ void nms_prep_rows(const int* __restrict__ H) {
    int warp = (blockIdx.x * blockDim.x + threadIdx.x) >> 5;
    int lane = threadIdx.x & 31;
    if (warp >= MR_ROWS) return;
    const int* row = H + warp * N_COLS;

    int vals[NCHUNK];
    #pragma unroll
    for (int j = 0; j < NCHUNK; ++j) vals[j] = row[j * 32 + lane];

    int cnt = 0;
    #pragma unroll
    for (int j = 0; j < NCHUNK; ++j) {
        unsigned ball = __ballot_sync(0xffffffffu, vals[j] != 0);
        if (lane == 0) {
            g_row_mask[warp][j]  = ball;
            g_row_pref8[warp][j] = (unsigned char)cnt;
        }
        int before = __popc(ball & ((1u << lane) - 1u));
        if (vals[j] != 0) g_row_cols[warp * ROW_DEG + cnt + before] = j * 32 + lane;
        cnt += __popc(ball);
    }
}

// ---------------------------------------------------------------------------
// Kernel 2: column lists — ONE WARP PER COLUMN (576 warps total). 5 batched
// loads + 5 ballots per warp; no serial 144-iteration loop anywhere.
// Edges emitted in ascending row order -> deterministic summation order.
// ---------------------------------------------------------------------------
#define CB_J 5                         // ceil(144/32) row rounds per column
__global__ void nms_colbuild() {
    const int c    = (blockIdx.x * blockDim.x + threadIdx.x) >> 5;  // column id
    const int lane = threadIdx.x & 31;
    if (c >= N_COLS) return;
    const int cw = c >> 5;
    const int cb = c & 31;
    const unsigned colbelow = (1u << cb) - 1u;
    const unsigned lanebelow = (1u << lane) - 1u;

    unsigned mask[CB_J];
    unsigned char pref[CB_J];
    #pragma unroll
    for (int j = 0; j < CB_J; ++j) {
        int m = j * 32 + lane;
        if (m < MR_ROWS) {
            mask[j] = g_row_mask[m][cw];
            pref[j] = g_row_pref8[m][cw];
        } else {
            mask[j] = 0u; pref[j] = 0;
        }
    }

    int cnt = 0;
    #pragma unroll
    for (int j = 0; j < CB_J; ++j) {
        const int m = j * 32 + lane;
        const bool hit = (m < MR_ROWS) && ((mask[j] >> cb) & 1u);
        unsigned ball = __ballot_sync(0xffffffffu, hit);
        int before = __popc(ball & lanebelow);
        if (hit) {
            int slot = (int)pref[j] + __popc(mask[j] & colbelow);
            g_ce16[c * CE_STRIDE + 1 + cnt + before] =
                (unsigned short)(m * ROW_DEG + slot);
        }
        cnt += __popc(ball);
    }
    if (lane == 0) g_ce16[c * CE_STRIDE] = (unsigned short)cnt;
}

// ---------------------------------------------------------------------------
// Kernel 3: decoder. ONE frame per CTA (grid 256 -> 2 CTAs/SM, latencies of
// the two CTAs overlap each other's barrier stalls). No atomics, no zeroing
// loop (gather fully overwrites sumE), 2 barriers per iteration, all sumE
// loads for the 9 passes batched up-front.
// ---------------------------------------------------------------------------
__global__ __launch_bounds__(BT) void nms_decode(
    const float* __restrict__ r,
    const float* __restrict__ alpha,
    const float* __restrict__ beta,
    float* __restrict__ out)
{
    __shared__ float s_r[N_COLS];
    __shared__ float s_sumE[N_COLS];
    __shared__ float s_E[N_MSG];
    __shared__ float s_a[NB_A];
    __shared__ float s_b[NB_A];
    __shared__ __align__(16) unsigned short s_ce[N_COLS * CE_STRIDE];

    const int tid  = threadIdx.x;          // 0..255
    const int grp  = tid >> 4;             // 16-lane row group (0..15)
    const int k    = tid & 15;             // edge slot (15 = padding)
    const int b    = blockIdx.x;
    const bool act = (k < ROW_DEG);
    const unsigned hmask = 0xFFFFu << (tid & 16);

    // ---- stage inputs (all loads batched / coalesced) ----
    for (int i = tid; i < NB_A; i += BT) { s_a[i] = alpha[i]; s_b[i] = beta[i]; }
    {   // edge lists as uint4: 576*16 ushort = 1152 uint4
        const uint4* src = (const uint4*)g_ce16;
        uint4* dst = (uint4*)s_ce;
        #pragma unroll
        for (int i = 0; i < (N_COLS * CE_STRIDE) / 8 / BT + 1; ++i) {
            int idx = tid + i * BT;
            if (idx < (N_COLS * CE_STRIDE) / 8) dst[idx] = src[idx];
        }
    }
    for (int i = tid; i < N_COLS; i += BT) {
        s_r[i] = r[b * N_COLS + i];
        s_sumE[i] = 0.0f;
    }

    // ---- per-edge register state (9 edges per thread) ----
    int   rc[NPASS];
    int   aoff[NPASS];
    float rv[NPASS];
    float Ep[NPASS];
    #pragma unroll
    for (int p = 0; p < NPASS; ++p) {
        int row = p * 16 + grp;
        int e = row * ROW_DEG + (act ? k : 0);
        rc[p] = act ? g_row_cols[e] : 0;                 // batched LDG
        Ep[p] = 0.0f;
    }
    #pragma unroll
    for (int p = 0; p < NPASS; ++p) {
        int row = p * 16 + grp;
        aoff[p] = (row / Z_LIFT) * ((N_COLS / Z_LIFT) * N_IT)
                + (rc[p] / Z_LIFT) * N_IT;
    }
    __syncthreads();
    #pragma unroll
    for (int p = 0; p < NPASS; ++p) rv[p] = s_r[rc[p]];

    for (int it = 0; it < N_IT; ++it) {
        // ---- batch all sumE reads (MLP 9) ----
        float v[NPASS];
        #pragma unroll
        for (int p = 0; p < NPASS; ++p)
            v[p] = rv[p] + s_sumE[rc[p]] - Ep[p];

        // ---- check-node phase ----
        #pragma unroll
        for (int p = 0; p < NPASS; ++p) {
            float av = act ? fabsf(v[p]) : INFINITY;

            unsigned negb = __ballot_sync(0xffffffffu, act && (v[p] < 0.0f));
            int parity = __popc(negb & hmask) & 1;

            float m1 = av, m2 = INFINITY;
            int   k1 = k;
            #pragma unroll
            for (int d = 1; d < 16; d <<= 1) {
                float om1 = __shfl_xor_sync(0xffffffffu, m1, d, 16);
                float om2 = __shfl_xor_sync(0xffffffffu, m2, d, 16);
                int   ok1 = __shfl_xor_sync(0xffffffffu, k1, d, 16);
                if (om1 < m1) { m2 = fminf(m1, om2); m1 = om1; k1 = ok1; }
                else          { m2 = fminf(m2, om1); }
            }

            if (act) {
                float sel = (k == k1) ? m2 : m1;          // exclude self at argmin
                int   ai  = aoff[p] + it;
                float mag = fmaxf(sel - s_b[ai], 0.0f);
                int neg = parity ^ ((v[p] < 0.0f) ? 1 : 0);
                float E = s_a[ai] * mag;
                E = neg ? -E : E;
                E = (m1 == 0.0f) ? 0.0f : E;              // zero in row -> E = 0
                Ep[p] = E;
                s_E[(p * 16 + grp) * ROW_DEG + k] = E;
            }
        }
        __syncthreads();

        // ---- column-sum phase: fixed-stride gather, fully overwrites sumE ----
        for (int c = tid; c < N_COLS; c += BT) {
            const unsigned short* ce = &s_ce[c * CE_STRIDE];
            int deg = ce[0];
            float s = 0.0f;
            for (int j = 1; j <= deg; ++j) s += s_E[ce[j]];
            s_sumE[c] = s;
        }
        __syncthreads();
    }

    // Posterior LLRs
    for (int i = tid; i < N_COLS; i += BT)
        out[b * N_COLS + i] = s_r[i] + s_sumE[i];
}

extern "C" void kernel_launch(void* const* d_in, const int* in_sizes, int n_in,
                              void* d_out, int out_size) {
    const float* r     = (const float*)d_in[0];   // (256, 576)
    const float* alpha = (const float*)d_in[1];   // (6, 24, 3)
    const float* beta  = (const float*)d_in[2];   // (6, 24, 3)
    const int*   H     = (const int*)d_in[3];     // (144, 576)
    float* out = (float*)d_out;                   // (256, 576)

    nms_prep_rows<<<18, 256>>>(H);
    nms_colbuild<<<18, 1024>>>();                 // one warp per column
    nms_decode<<<B_FRAMES, BT>>>(r, alpha, beta, out);
}

// round 14
// speedup vs baseline: 1.8133x; 1.0108x over previous
#include <cuda_runtime.h>
#include <math.h>

// Problem constants (fixed by the reference)
#define B_FRAMES 256
#define N_COLS   576
#define MR_ROWS  144
#define Z_LIFT   24
#define N_IT     3
#define ROW_DEG  15
#define N_MSG    (MR_ROWS * ROW_DEG)   // 2160
#define NB_A     ((MR_ROWS / Z_LIFT) * (N_COLS / Z_LIFT) * N_IT)  // 432
#define NCHUNK   (N_COLS / 32)         // 18 column chunks per row

#define BT    256                      // decode threads per CTA (1 frame/CTA)
#define NPASS (MR_ROWS / 16)           // 9 row passes (16-lane groups)
#define QMAX  16                       // padded column depth (max col degree < 16)

// Graph scratch (rebuilt from H each launch; every slot written each launch)
__device__ unsigned g_row_mask[MR_ROWS][NCHUNK];       // per-row 32-col occupancy
__device__ unsigned char g_row_pref8[MR_ROWS][NCHUNK]; // #ones before this chunk
// Per-edge packed info, indexed e = m*15 + slot:
//   bits[0:10)=c  bits[10:14)=q(col rank)  bits[14:17)=m/24  bits[17:22)=c/24
__device__ int g_einfo[N_MSG];

// ---------------------------------------------------------------------------
// Kernel 1: row bitmasks + prefix counts. One warp per row, loads batched.
// ---------------------------------------------------------------------------
__global__ void nms_prep_rows(const int* __restrict__ H) {
    int warp = (blockIdx.x * blockDim.x + threadIdx.x) >> 5;
    int lane = threadIdx.x & 31;
    if (warp >= MR_ROWS) return;
    const int* row = H + warp * N_COLS;

    int vals[NCHUNK];
    #pragma unroll
    for (int j = 0; j < NCHUNK; ++j) vals[j] = row[j * 32 + lane];

    int cnt = 0;
    #pragma unroll
    for (int j = 0; j < NCHUNK; ++j) {
        unsigned ball = __ballot_sync(0xffffffffu, vals[j] != 0);
        if (lane == 0) {
            g_row_mask[warp][j]  = ball;
            g_row_pref8[warp][j] = (unsigned char)cnt;
        }
        cnt += __popc(ball);
    }
}

// ---------------------------------------------------------------------------
// Kernel 2: per-edge packed info — ONE WARP PER COLUMN (576 warps).
// q assigned in ascending row order (deterministic, matches gather order).
// ---------------------------------------------------------------------------
#define CB_J 5                         // ceil(144/32) row rounds per column
__global__ void nms_colbuild() {
    const int c    = (blockIdx.x * blockDim.x + threadIdx.x) >> 5;
    const int lane = threadIdx.x & 31;
    if (c >= N_COLS) return;
    const int cw = c >> 5;
    const int cb = c & 31;
    const unsigned colbelow  = (1u << cb) - 1u;
    const unsigned lanebelow = (1u << lane) - 1u;

    unsigned mask[CB_J];
    unsigned char pref[CB_J];
    #pragma unroll
    for (int j = 0; j < CB_J; ++j) {
        int m = j * 32 + lane;
        if (m < MR_ROWS) { mask[j] = g_row_mask[m][cw]; pref[j] = g_row_pref8[m][cw]; }
        else             { mask[j] = 0u; pref[j] = 0; }
    }

    int cnt = 0;
    #pragma unroll
    for (int j = 0; j < CB_J; ++j) {
        const int m = j * 32 + lane;
        const bool hit = (m < MR_ROWS) && ((mask[j] >> cb) & 1u);
        unsigned ball = __ballot_sync(0xffffffffu, hit);
        int before = __popc(ball & lanebelow);
        if (hit) {
            int slot = (int)pref[j] + __popc(mask[j] & colbelow);
            int q = cnt + before;
            g_einfo[m * ROW_DEG + slot] =
                c | (q << 10) | ((m / Z_LIFT) << 14) | ((c / Z_LIFT) << 17);
        }
        cnt += __popc(ball);
    }
}

// ---------------------------------------------------------------------------
// Kernel 3: decoder. One frame per CTA (grid 256 -> 2 CTAs/SM).
// E written directly column-major (zero-padded slab) -> gather is 16
// independent conflict-free LDS + tree add: no index loads, no atomics.
// ---------------------------------------------------------------------------
__global__ __launch_bounds__(BT) void nms_decode(
    const float* __restrict__ r,
    const float* __restrict__ alpha,
    const float* __restrict__ beta,
    float* __restrict__ out)
{
    __shared__ float s_Ecol[QMAX * N_COLS];   // 36864 B, column-major, zero-padded
    __shared__ float s_r[N_COLS];
    __shared__ float s_sumE[N_COLS];
    __shared__ float s_a[NB_A];
    __shared__ float s_b[NB_A];

    const int tid  = threadIdx.x;          // 0..255
    const int grp  = tid >> 4;             // 16-lane row group (0..15)
    const int k    = tid & 15;             // edge slot (15 = padding)
    const int b    = blockIdx.x;
    const int lane32 = tid & 31;
    const bool act = (k < ROW_DEG);
    const unsigned hmask = 0xFFFFu << (tid & 16);

    // ---- single batched staging round (all loads independent) ----
    int ew[NPASS];
    #pragma unroll
    for (int p = 0; p < NPASS; ++p) {
        int e = (p * 16 + grp) * ROW_DEG + (act ? k : 0);
        ew[p] = g_einfo[e];
    }
    for (int i = tid; i < NB_A; i += BT) { s_a[i] = alpha[i]; s_b[i] = beta[i]; }
    for (int i = tid; i < N_COLS; i += BT) s_r[i] = r[b * N_COLS + i];
    {   // zero the E slab (float4)
        float4* z = (float4*)s_Ecol;
        #pragma unroll
        for (int i = 0; i < (QMAX * N_COLS) / 4 / BT; ++i)
            z[tid + i * BT] = make_float4(0.f, 0.f, 0.f, 0.f);
    }

    // ---- unpack per-edge constants ----
    int   cc[NPASS], wpos[NPASS], aoff[NPASS];
    float rv[NPASS], Ep[NPASS];
    #pragma unroll
    for (int p = 0; p < NPASS; ++p) {
        int w = act ? ew[p] : 0;
        cc[p]   = w & 1023;
        wpos[p] = ((w >> 10) & 15) * N_COLS + cc[p];
        aoff[p] = ((w >> 14) & 7) * ((N_COLS / Z_LIFT) * N_IT)
                + ((w >> 17) & 31) * N_IT;
        Ep[p]   = 0.0f;
    }
    __syncthreads();
    #pragma unroll
    for (int p = 0; p < NPASS; ++p) rv[p] = s_r[cc[p]];

    for (int it = 0; it < N_IT; ++it) {
        // ---- v->c messages, all sumE reads batched (MLP 9) ----
        float v[NPASS];
        if (it == 0) {
            #pragma unroll
            for (int p = 0; p < NPASS; ++p) v[p] = rv[p];
        } else {
            #pragma unroll
            for (int p = 0; p < NPASS; ++p)
                v[p] = rv[p] + s_sumE[cc[p]] - Ep[p];
        }

        // ---- check-node phase ----
        #pragma unroll
        for (int p = 0; p < NPASS; ++p) {
            float av = act ? fabsf(v[p]) : INFINITY;

            unsigned negb = __ballot_sync(0xffffffffu, act && (v[p] < 0.0f));
            int parity = __popc(negb & hmask) & 1;

            // min over group (4 shfl)
            float m1 = av;
            #pragma unroll
            for (int d = 1; d < 16; d <<= 1)
                m1 = fminf(m1, __shfl_xor_sync(0xffffffffu, m1, d, 16));
            // first argmin lane (ascending column order -> reference tie-break)
            unsigned bm = __ballot_sync(0xffffffffu, av == m1) & hmask;
            const bool isl = (lane32 == (__ffs(bm) - 1));
            // second min: leader's value masked out (4 shfl)
            float m2 = isl ? INFINITY : av;
            #pragma unroll
            for (int d = 1; d < 16; d <<= 1)
                m2 = fminf(m2, __shfl_xor_sync(0xffffffffu, m2, d, 16));

            if (act) {
                int   ai  = aoff[p] + it;
                float sel = isl ? m2 : m1;
                float mag = fmaxf(sel - s_b[ai], 0.0f);
                float E = s_a[ai] * mag;
                int neg = parity ^ ((v[p] < 0.0f) ? 1 : 0);
                E = neg ? -E : E;
                E = (m1 == 0.0f) ? 0.0f : E;      // zero in row -> whole row E=0
                Ep[p] = E;
                s_Ecol[wpos[p]] = E;
            }
        }
        __syncthreads();

        // ---- column sums: 16 independent conflict-free LDS + tree add ----
        if (it < N_IT - 1) {
            for (int c = tid; c < N_COLS; c += BT) {
                float x[QMAX];
                #pragma unroll
                for (int q = 0; q < QMAX; ++q) x[q] = s_Ecol[q * N_COLS + c];
                float s = ((x[0]+x[1])+(x[2]+x[3])) + ((x[4]+x[5])+(x[6]+x[7]))
                        + (((x[8]+x[9])+(x[10]+x[11])) + ((x[12]+x[13])+(x[14]+x[15])));
                s_sumE[c] = s;
            }
            __syncthreads();
        } else {
            // fused epilogue: posterior LLRs straight to GMEM
            for (int c = tid; c < N_COLS; c += BT) {
                float x[QMAX];
                #pragma unroll
                for (int q = 0; q < QMAX; ++q) x[q] = s_Ecol[q * N_COLS + c];
                float s = ((x[0]+x[1])+(x[2]+x[3])) + ((x[4]+x[5])+(x[6]+x[7]))
                        + (((x[8]+x[9])+(x[10]+x[11])) + ((x[12]+x[13])+(x[14]+x[15])));
                out[b * N_COLS + c] = s_r[c] + s;
            }
        }
    }
}

extern "C" void kernel_launch(void* const* d_in, const int* in_sizes, int n_in,
                              void* d_out, int out_size) {
    const float* r     = (const float*)d_in[0];   // (256, 576)
    const float* alpha = (const float*)d_in[1];   // (6, 24, 3)
    const float* beta  = (const float*)d_in[2];   // (6, 24, 3)
    const int*   H     = (const int*)d_in[3];     // (144, 576)
    float* out = (float*)d_out;                   // (256, 576)

    nms_prep_rows<<<18, 256>>>(H);
    nms_colbuild<<<18, 1024>>>();                 // one warp per column
    nms_decode<<<B_FRAMES, BT>>>(r, alpha, beta, out);
}

// round 15
// speedup vs baseline: 1.9231x; 1.0606x over previous
#include <cuda_runtime.h>
#include <math.h>

// Problem constants (fixed by the reference)
#define B_FRAMES 256
#define N_COLS   576
#define MR_ROWS  144
#define Z_LIFT   24
#define N_IT     3
#define ROW_DEG  15
#define N_MSG    (MR_ROWS * ROW_DEG)   // 2160
#define NB_A     ((MR_ROWS / Z_LIFT) * (N_COLS / Z_LIFT) * N_IT)  // 432
#define NCHUNK   (N_COLS / 32)         // 18 column chunks per row

#define BT    256                      // threads per CTA (1 frame/CTA)
#define GRID  B_FRAMES                 // 256 CTAs, 2/SM -> all co-resident
#define NPASS (MR_ROWS / 16)           // 9 row passes (16-lane groups)
#define QMAX  16                       // padded column depth (max col degree < 16)
#define CB_J  5                        // ceil(144/32) row rounds per column

// Graph scratch (rebuilt from H each launch; every slot written each launch)
__device__ unsigned g_row_mask[MR_ROWS][NCHUNK];
__device__ unsigned char g_row_pref8[MR_ROWS][NCHUNK];
// Per-edge packed info, e = m*15+slot:
//   bits[0:10)=c  [10:14)=q(col rank)  [14:17)=m/24  [17:22)=c/24
__device__ int g_einfo[N_MSG];

// Monotonic grid-barrier counter. Never reset: target arithmetic is
// launch-invariant ((old/GRID+1)*GRID), so graph replays are safe.
__device__ unsigned long long g_bar;

__device__ __forceinline__ void grid_barrier() {
    __syncthreads();
    if (threadIdx.x == 0) {
        __threadfence();
        unsigned long long old = atomicAdd(&g_bar, 1ULL);
        unsigned long long target = (old / GRID + 1ULL) * GRID;
        while (*(volatile unsigned long long*)&g_bar < target) __nanosleep(64);
        __threadfence();
    }
    __syncthreads();
}

// ---------------------------------------------------------------------------
// Single fused kernel: [stage + row masks] -> gbar -> [column einfo] -> gbar
// -> [decode]. All 256 CTAs are co-resident (2/SM), so the barriers are safe.
// ---------------------------------------------------------------------------
__global__ __launch_bounds__(BT) void nms_fused(
    const int*   __restrict__ H,
    const float* __restrict__ r,
    const float* __restrict__ alpha,
    const float* __restrict__ beta,
    float* __restrict__ out)
{
    __shared__ float s_Ecol[QMAX * N_COLS];   // 36864 B column-major, zero-padded
    __shared__ float s_r[N_COLS];
    __shared__ float s_sumE[N_COLS];
    __shared__ float s_a[NB_A];
    __shared__ float s_b[NB_A];

    const int tid    = threadIdx.x;        // 0..255
    const int b      = blockIdx.x;
    const int wid    = tid >> 5;
    const int lane   = tid & 31;
    const int grp    = tid >> 4;           // 16-lane row group (0..15)
    const int k      = tid & 15;           // edge slot (15 = padding)
    const bool act   = (k < ROW_DEG);
    const unsigned hmask = 0xFFFFu << (tid & 16);

    // ---- stage frame inputs (independent of graph structure) ----
    for (int i = tid; i < NB_A; i += BT) { s_a[i] = alpha[i]; s_b[i] = beta[i]; }
    for (int i = tid; i < N_COLS; i += BT) s_r[i] = r[b * N_COLS + i];
    {
        float4* z = (float4*)s_Ecol;
        #pragma unroll
        for (int i = 0; i < (QMAX * N_COLS) / 4 / BT; ++i)
            z[tid + i * BT] = make_float4(0.f, 0.f, 0.f, 0.f);
    }

    // ---- phase A: row bitmasks (CTAs 0..17, one warp per row) ----
    {
        const int row = b * 8 + wid;       // 18 CTAs x 8 warps = 144 rows
        if (b < 18 && row < MR_ROWS) {
            const int* hr = H + row * N_COLS;
            int vals[NCHUNK];
            #pragma unroll
            for (int j = 0; j < NCHUNK; ++j) vals[j] = hr[j * 32 + lane];
            int cnt = 0;
            #pragma unroll
            for (int j = 0; j < NCHUNK; ++j) {
                unsigned ball = __ballot_sync(0xffffffffu, vals[j] != 0);
                if (lane == 0) {
                    g_row_mask[row][j]  = ball;
                    g_row_pref8[row][j] = (unsigned char)cnt;
                }
                cnt += __popc(ball);
            }
        }
    }
    grid_barrier();

    // ---- phase B: per-edge packed info (CTAs 0..71, one warp per column) ----
    {
        const int c = b * 8 + wid;         // 72 CTAs x 8 warps = 576 columns
        if (b < 72 && c < N_COLS) {
            const int cw = c >> 5, cb = c & 31;
            const unsigned colbelow  = (1u << cb) - 1u;
            const unsigned lanebelow = (1u << lane) - 1u;
            unsigned mask[CB_J];
            unsigned char pref[CB_J];
            #pragma unroll
            for (int j = 0; j < CB_J; ++j) {
                int m = j * 32 + lane;
                if (m < MR_ROWS) { mask[j] = g_row_mask[m][cw]; pref[j] = g_row_pref8[m][cw]; }
                else             { mask[j] = 0u; pref[j] = 0; }
            }
            int cnt = 0;
            #pragma unroll
            for (int j = 0; j < CB_J; ++j) {
                const int m = j * 32 + lane;
                const bool hit = (m < MR_ROWS) && ((mask[j] >> cb) & 1u);
                unsigned ball = __ballot_sync(0xffffffffu, hit);
                int before = __popc(ball & lanebelow);
                if (hit) {
                    int slot = (int)pref[j] + __popc(mask[j] & colbelow);
                    int q = cnt + before;
                    g_einfo[m * ROW_DEG + slot] =
                        c | (q << 10) | ((m / Z_LIFT) << 14) | ((c / Z_LIFT) << 17);
                }
                cnt += __popc(ball);
            }
        }
    }
    grid_barrier();

    // ---- phase C: decode this CTA's frame ----
    int ew[NPASS];
    #pragma unroll
    for (int p = 0; p < NPASS; ++p) {
        int e = (p * 16 + grp) * ROW_DEG + (act ? k : 0);
        ew[p] = g_einfo[e];                // L2-hot after phase B
    }
    int   cc[NPASS], wpos[NPASS], aoff[NPASS];
    float rv[NPASS], Ep[NPASS];
    #pragma unroll
    for (int p = 0; p < NPASS; ++p) {
        int w = act ? ew[p] : 0;
        cc[p]   = w & 1023;
        wpos[p] = ((w >> 10) & 15) * N_COLS + cc[p];
        aoff[p] = ((w >> 14) & 7) * ((N_COLS / Z_LIFT) * N_IT)
                + ((w >> 17) & 31) * N_IT;
        Ep[p]   = 0.0f;
    }
    #pragma unroll
    for (int p = 0; p < NPASS; ++p) rv[p] = s_r[cc[p]];

    for (int it = 0; it < N_IT; ++it) {
        float v[NPASS];
        if (it == 0) {
            #pragma unroll
            for (int p = 0; p < NPASS; ++p) v[p] = rv[p];
        } else {
            #pragma unroll
            for (int p = 0; p < NPASS; ++p)
                v[p] = rv[p] + s_sumE[cc[p]] - Ep[p];
        }

        #pragma unroll
        for (int p = 0; p < NPASS; ++p) {
            float av = act ? fabsf(v[p]) : INFINITY;

            unsigned negb = __ballot_sync(0xffffffffu, act && (v[p] < 0.0f));
            int parity = __popc(negb & hmask) & 1;

            float m1 = av;
            #pragma unroll
            for (int d = 1; d < 16; d <<= 1)
                m1 = fminf(m1, __shfl_xor_sync(0xffffffffu, m1, d, 16));
            unsigned bm = __ballot_sync(0xffffffffu, av == m1) & hmask;
            const bool isl = ((tid & 31) == (__ffs(bm) - 1));  // first argmin
            float m2 = isl ? INFINITY : av;
            #pragma unroll
            for (int d = 1; d < 16; d <<= 1)
                m2 = fminf(m2, __shfl_xor_sync(0xffffffffu, m2, d, 16));

            if (act) {
                int   ai  = aoff[p] + it;
                float sel = isl ? m2 : m1;
                float mag = fmaxf(sel - s_b[ai], 0.0f);
                float E = s_a[ai] * mag;
                int neg = parity ^ ((v[p] < 0.0f) ? 1 : 0);
                E = neg ? -E : E;
                E = (m1 == 0.0f) ? 0.0f : E;     // zero in row -> whole row E=0
                Ep[p] = E;
                s_Ecol[wpos[p]] = E;
            }
        }
        __syncthreads();

        if (it < N_IT - 1) {
            for (int c = tid; c < N_COLS; c += BT) {
                float x[QMAX];
                #pragma unroll
                for (int q = 0; q < QMAX; ++q) x[q] = s_Ecol[q * N_COLS + c];
                float s = ((x[0]+x[1])+(x[2]+x[3])) + ((x[4]+x[5])+(x[6]+x[7]))
                        + (((x[8]+x[9])+(x[10]+x[11])) + ((x[12]+x[13])+(x[14]+x[15])));
                s_sumE[c] = s;
            }
            __syncthreads();
        } else {
            for (int c = tid; c < N_COLS; c += BT) {
                float x[QMAX];
                #pragma unroll
                for (int q = 0; q < QMAX; ++q) x[q] = s_Ecol[q * N_COLS + c];
                float s = ((x[0]+x[1])+(x[2]+x[3])) + ((x[4]+x[5])+(x[6]+x[7]))
                        + (((x[8]+x[9])+(x[10]+x[11])) + ((x[12]+x[13])+(x[14]+x[15])));
                out[b * N_COLS + c] = s_r[c] + s;
            }
        }
    }
}

extern "C" void kernel_launch(void* const* d_in, const int* in_sizes, int n_in,
                              void* d_out, int out_size) {
    const int*   H     = (const int*)d_in[3];     // (144, 576)
    const float* r     = (const float*)d_in[0];   // (256, 576)
    const float* alpha = (const float*)d_in[1];   // (6, 24, 3)
    const float* beta  = (const float*)d_in[2];   // (6, 24, 3)
    float* out = (float*)d_out;                   // (256, 576)

    nms_fused<<<GRID, BT>>>(H, r, alpha, beta, out);
}